// round 16
// baseline (speedup 1.0000x reference)
#include <cuda_runtime.h>
#include <math.h>

namespace {

constexpr int P     = 13;
constexpr int TPB   = 512;
constexpr int D     = 64;
constexpr int NWARP = TPB / 32;

struct c32 { float x, y; };
typedef unsigned long long u64;

__device__ __forceinline__ c32 cmul(c32 a, c32 b) {
    return { fmaf(a.x, b.x, -a.y * b.y), fmaf(a.x, b.y, a.y * b.x) };
}

// ---------------- packed f32x2 helpers ----------------
__device__ __forceinline__ u64 pk2(float x, float y) {
    u64 r; asm("mov.b64 %0, {%1, %2};" : "=l"(r) : "f"(x), "f"(y)); return r;
}
__device__ __forceinline__ void upk2(u64 v, float& x, float& y) {
    asm("mov.b64 {%0, %1}, %2;" : "=f"(x), "=f"(y) : "l"(v));
}
__device__ __forceinline__ u64 swp2(u64 v) {
    u64 r;
    asm("{ .reg .b32 lo, hi; mov.b64 {lo, hi}, %1; mov.b64 %0, {hi, lo}; }"
        : "=l"(r) : "l"(v));
    return r;
}
__device__ __forceinline__ u64 mul2(u64 a, u64 b) {
    u64 r; asm("mul.rn.f32x2 %0, %1, %2;" : "=l"(r) : "l"(a), "l"(b)); return r;
}
__device__ __forceinline__ u64 fma2(u64 a, u64 b, u64 c) {
    u64 r; asm("fma.rn.f32x2 %0, %1, %2, %3;" : "=l"(r) : "l"(a), "l"(b), "l"(c)); return r;
}
// n = m0*va + m1*vb  (complex, packed):  va,vb packed {x,y}; vas,vbs their swaps {y,x}
__device__ __forceinline__ u64 bfly(u64 va, u64 vas, u64 vb, u64 vbs,
                                    u64 m0xx, u64 m0yn, u64 m1xx, u64 m1yn) {
    return fma2(va, m0xx, fma2(vas, m0yn, fma2(vb, m1xx, mul2(vbs, m1yn))));
}

// ---------------- compile-time GF(2) machinery ----------------

__host__ __device__ constexpr int cg_cnot(int i, int x) {
    int cb = P - 1 - i;
    int tb = P - 1 - ((i + 1) % P);
    return ((x >> cb) & 1) ? (x ^ (1 << tb)) : x;
}
__host__ __device__ constexpr int cGmap(int y) {
    for (int i = P - 1; i >= 0; --i) y = cg_cnot(i, y);
    return y;
}
__host__ __device__ constexpr int cGinv(int y) {
    for (int i = 0; i < P; i++) y = cg_cnot(i, y);
    return y;
}
__host__ __device__ constexpr int cpop(int x) { int c = 0; for (int i = 0; i < 16; i++) c += (x >> i) & 1; return c; }
__host__ __device__ constexpr int cctz(int x) { for (int i = 0; i < 16; i++) if ((x >> i) & 1) return i; return -1; }

struct QCData {
    int m2[P];            // layer-2 pair masks  G(e_w)
    int r2[P];            // layer-2 orientation masks (rows of G^-1)
    int rm[P];            // measurement parity masks (rows of G^-2)
    int npos[3][9];       // non-pivot bit positions per batch (ascending)
    int combo[3][16];     // XOR offsets of the 16 coset members
    int lm[3][4];         // local 4-bit pair pattern per gate
    int lml[3][4];        // lowest set bit of lm (canonical selector)
    int lr[3][4];         // local parity pattern per gate
    int rw[3][4];         // full orientation mask per gate (for px)
    int odm[8];           // measurement: per-jj orientation delta (compile-time)
    int mg[4];            // measurement: WHT sig generators
    int kw[P];            // measurement: WHT coefficient index per wire
};

__host__ __device__ constexpr QCData make_qc() {
    QCData q{};
    for (int w = 0; w < P; w++) {
        q.m2[w] = cGmap(1 << (P - 1 - w));
        int r = 0, rm = 0;
        for (int p = 0; p < P; p++) {
            int gi  = cGinv(1 << p);
            int gi2 = cGinv(gi);
            r  |= ((gi  >> (P - 1 - w)) & 1) << p;
            rm |= ((gi2 >> (P - 1 - w)) & 1) << p;
        }
        q.r2[w] = r; q.rm[w] = rm;
    }
    for (int b = 0; b < 3; b++) {
        int f[4] = {}, piv[4] = {};
        for (int i = 0; i < 4; i++) f[i] = q.m2[4 * b + i];
        for (int i = 0; i < 4; i++) {
            for (int j = 0; j < i; j++) if ((f[i] >> piv[j]) & 1) f[i] ^= f[j];
            piv[i] = cctz(f[i]);
            for (int j = 0; j < i; j++) if ((f[j] >> piv[i]) & 1) f[j] ^= f[i];
        }
        int np = 0;
        for (int bit = 0; bit < P; bit++) {
            bool isp = false;
            for (int i = 0; i < 4; i++) if (piv[i] == bit) isp = true;
            if (!isp) q.npos[b][np++] = bit;
        }
        for (int j = 0; j < 16; j++) {
            int c = 0;
            for (int i = 0; i < 4; i++) if ((j >> i) & 1) c ^= f[i];
            q.combo[b][j] = c;
        }
        for (int g = 0; g < 4; g++) {
            int m = q.m2[4 * b + g], r = q.r2[4 * b + g];
            int lm = 0, lr = 0;
            for (int i = 0; i < 4; i++) {
                lm |= ((m >> piv[i]) & 1) << i;
                lr |= (cpop(f[i] & r) & 1) << i;
            }
            q.lm[b][g] = lm;
            q.lml[b][g] = lm & (-lm);
            q.lr[b][g] = lr;
            q.rw[b][g] = r;
        }
    }
    // measurement constants (final gate on wire 12 fused with <Z> readout)
    {
        int m12 = q.m2[12], r12 = q.r2[12];
        for (int jj = 0; jj < 8; jj++) q.odm[jj] = cpop((jj << 10) & r12) & 1;
        for (int i = 0; i < 4; i++) {
            int v = (i < 3) ? (1024 << i) : m12;    // idx-bit deltas in amp-index space
            int sgn = 0;
            for (int w = 0; w < P; w++) sgn |= (cpop(v & q.rm[w]) & 1) << w;
            q.mg[i] = sgn;
        }
        for (int w = 0; w < P; w++) {
            int k = 0;
            for (int i = 0; i < 4; i++) k |= ((q.mg[i] >> w) & 1) << i;
            q.kw[w] = k;
        }
    }
    return q;
}

// host-side structural checks only (device code re-materializes its own local constexpr copy)
constexpr QCData QC_HOST = make_qc();
__host__ __device__ constexpr int batch2_support() {
    int s = 0;
    for (int j = 0; j < 16; j++) s |= QC_HOST.combo[2][j];
    return s;
}
static_assert((QC_HOST.m2[12] & 1) == 1, "insert for final gate must be <<1");
static_assert(QC_HOST.npos[2][0] == 4 && QC_HOST.npos[2][8] == 12, "batch2 coset must be low-bit");
static_assert((batch2_support() & ~0x1F) == 0, "batch2 combos must live in bits 0..4");

// SMEM bank-conflict swizzle: XOR bits[7:4] into bits[3:0]. Bijection on [0,8192).
__device__ __forceinline__ int sw(int y) { return y ^ ((y >> 4) & 0xF); }

// ---------------- SMEM layout (floats) ----------------
// State region doubles as the reduction scratch (13*512 floats) after measurement reads.
constexpr int SM_S    = 0;                    // 8192 c32 = 16384 floats
constexpr int SM_COLA = 16384;                // 13*2 c32 = 52 floats (8B aligned)
constexpr int SM_SPL  = 16436;                // 13 gates * 8 u64 splats = 208 floats (8B aligned)
constexpr int SM_EXPV = 16644;                // 13 floats
constexpr int SMEM_BYTES = (16644 + 13 + 3) * 4;

// Apply 4 masked gates of batch B to the 16-amp packed register coset.
// Gate matrices come pre-splatted from SMEM: per gate 8 u64 =
// [xx(u00),yn(u00),xx(u01),yn(u01),xx(u10),yn(u10),xx(u11),yn(u11)].
// px reverses the element tuple (u00<->u11, u01<->u10); the oc-reversed tuple
// is the same registers renamed (compile-time), so pairs cost pure FMA2+swap.
template <int B>
__device__ __forceinline__ void apply_batch_gates(u64* __restrict__ reg,
                                                  const u64* __restrict__ sspl, int x)
{
    constexpr QCData qc = make_qc();
#pragma unroll
    for (int g = 0; g < 4; g++) {
        const u64* Sg = sspl + (4 * B + g) * 8;
        const u64 a0 = Sg[0], a1 = Sg[1], a2 = Sg[2], a3 = Sg[3];
        const u64 a4 = Sg[4], a5 = Sg[5], a6 = Sg[6], a7 = Sg[7];
        const bool px = (__popc(x & qc.rw[B][g]) & 1) != 0;
        const u64 E0xx = px ? a6 : a0, E0yn = px ? a7 : a1;
        const u64 E1xx = px ? a4 : a2, E1yn = px ? a5 : a3;
        const u64 E2xx = px ? a2 : a4, E2yn = px ? a3 : a5;
        const u64 E3xx = px ? a0 : a6, E3yn = px ? a1 : a7;
#pragma unroll
        for (int j = 0; j < 16; j++) {
            if (j & qc.lml[B][g]) continue;                  // canonical of each pair
            const int jp  = j ^ qc.lm[B][g];                 // compile-time partner
            const bool oc = (cpop(j & qc.lr[B][g]) & 1) != 0; // compile-time renaming
            const u64 m00xx = oc ? E3xx : E0xx, m00yn = oc ? E3yn : E0yn;
            const u64 m01xx = oc ? E2xx : E1xx, m01yn = oc ? E2yn : E1yn;
            const u64 m10xx = oc ? E1xx : E2xx, m10yn = oc ? E1yn : E2yn;
            const u64 m11xx = oc ? E0xx : E3xx, m11yn = oc ? E0yn : E3yn;
            const u64 va = reg[j], vb = reg[jp];
            const u64 vas = swp2(va), vbs = swp2(vb);
            reg[j]  = bfly(va, vas, vb, vbs, m00xx, m00yn, m01xx, m01yn);
            reg[jp] = bfly(va, vas, vb, vbs, m10xx, m10yn, m11xx, m11yn);
        }
    }
}

template <int B>
__device__ __forceinline__ void do_batch(u64* __restrict__ s64,
                                         const u64* __restrict__ sspl, int tid)
{
    constexpr QCData qc = make_qc();
    int x = 0;
#pragma unroll
    for (int i = 0; i < 9; i++) x |= ((tid >> i) & 1) << qc.npos[B][i];

    u64 reg[16];
#pragma unroll
    for (int j = 0; j < 16; j++) reg[j] = s64[sw(x ^ qc.combo[B][j])];

    apply_batch_gates<B>(reg, sspl, x);

#pragma unroll
    for (int j = 0; j < 16; j++) s64[sw(x ^ qc.combo[B][j])] = reg[j];
}

__global__ void __launch_bounds__(TPB, 2)
qlc_kernel(const float* __restrict__ h,
           const float* __restrict__ enc_w,
           const float* __restrict__ enc_b,
           const float* __restrict__ qw,
           const float* __restrict__ dec_w,
           const float* __restrict__ alpha,
           float* __restrict__ out)
{
    extern __shared__ float smemf[];
    u64*   s64  = (u64*)(smemf + SM_S);
    float* scr  = smemf + SM_S;              // reduction scratch (aliases dead state)
    c32*   colA = (c32*)(smemf + SM_COLA);   // [13][2] fused (enc+L1) column-0
    u64*   sspl = (u64*)(smemf + SM_SPL);    // [13][8] splatted layer-2 gate matrices
    float* expv = smemf + SM_EXPV;

    const int n = blockIdx.x, tid = threadIdx.x, wid = tid >> 5, lane = tid & 31;

    // ================= Phase A (fully parallel constants, fast sincos) =================
    // warps 0..12: wire w = wid — warp-reduced angles, lane 0 builds colA[w].
    // warp 13 lanes 0..12: shared layer-2 gate matrices, stored pre-splatted.
    if (wid < P) {
        const float* hrow = h + (n * P + wid) * D;
        const float h0 = hrow[lane], h1 = hrow[lane + 32];
        float aa[3];
#pragma unroll
        for (int a = 0; a < 3; a++) {
            float v = h0 * enc_w[a * D + lane] + h1 * enc_w[a * D + lane + 32];
#pragma unroll
            for (int off = 16; off; off >>= 1)
                v += __shfl_xor_sync(0xffffffffu, v, off);
            aa[a] = v;
        }
        if (lane == 0) {
            const int w = wid;
            float a0 = aa[0] + enc_b[0], a1 = aa[1] + enc_b[1], a2 = aa[2] + enc_b[2];
            float q0 = qw[w * 3 + 0], q1 = qw[w * 3 + 1], q2 = qw[w * 3 + 2];  // layer 0
            float sA, cA; __sincosf(0.5f * a0, &sA, &cA);
            c32 v0 = { cA, 0.f }, v1 = { 0.f, -sA };                 // RX col0
            float sB, cB; __sincosf(0.5f * a1, &sB, &cB);            // RY
            c32 t0 = { cB * v0.x - sB * v1.x, cB * v0.y - sB * v1.y };
            c32 t1 = { sB * v0.x + cB * v1.x, sB * v0.y + cB * v1.y };
            float sC, cC; __sincosf(0.5f * a2, &sC, &cC);            // RZ
            v0 = cmul({ cC, -sC }, t0); v1 = cmul({ cC, sC }, t1);
            float s0, c0; __sincosf(0.5f * q0, &s0, &c0);            // RY
            t0 = { c0 * v0.x - s0 * v1.x, c0 * v0.y - s0 * v1.y };
            t1 = { s0 * v0.x + c0 * v1.x, s0 * v0.y + c0 * v1.y };
            float s1, c1; __sincosf(0.5f * q1, &s1, &c1);            // RZ
            v0 = cmul({ c1, -s1 }, t0); v1 = cmul({ c1, s1 }, t1);
            float s2, c2; __sincosf(0.5f * q2, &s2, &c2);            // RY
            t0 = { c2 * v0.x - s2 * v1.x, c2 * v0.y - s2 * v1.y };
            t1 = { s2 * v0.x + c2 * v1.x, s2 * v0.y + c2 * v1.y };
            colA[w * 2 + 0] = t0; colA[w * 2 + 1] = t1;
        }
    } else if (wid == 13 && lane < P) {
        const int w = lane;
        float q0 = qw[(P + w) * 3 + 0], q1 = qw[(P + w) * 3 + 1], q2 = qw[(P + w) * 3 + 2]; // layer 1
        float s0, c0; __sincosf(0.5f * q0, &s0, &c0);
        float s1, c1; __sincosf(0.5f * q1, &s1, &c1);
        float s2, c2; __sincosf(0.5f * q2, &s2, &c2);
        // M1 = RZ(q1)*RY(q0)
        c32 e0 = { c1, -s1 }, e1 = { c1, s1 };
        c32 m00 = {  e0.x * c0,  e0.y * c0 }, m01 = { -e0.x * s0, -e0.y * s0 };
        c32 m10 = {  e1.x * s0,  e1.y * s0 }, m11 = {  e1.x * c0,  e1.y * c0 };
        // U = RY(q2)*M1
        c32 u00 = { c2 * m00.x - s2 * m10.x, c2 * m00.y - s2 * m10.y };
        c32 u01 = { c2 * m01.x - s2 * m11.x, c2 * m01.y - s2 * m11.y };
        c32 u10 = { s2 * m00.x + c2 * m10.x, s2 * m00.y + c2 * m10.y };
        c32 u11 = { s2 * m01.x + c2 * m11.x, s2 * m01.y + c2 * m11.y };
        u64* Sg = sspl + w * 8;
        Sg[0] = pk2(u00.x, u00.x); Sg[1] = pk2(-u00.y, u00.y);
        Sg[2] = pk2(u01.x, u01.x); Sg[3] = pk2(-u01.y, u01.y);
        Sg[4] = pk2(u10.x, u10.x); Sg[5] = pk2(-u10.y, u10.y);
        Sg[6] = pk2(u11.x, u11.x); Sg[7] = pk2(-u11.y, u11.y);
    }
    __syncthreads();

    // ---- product-state construction FUSED with batch-2 gates (registers only) ----
    {
        constexpr QCData qc = make_qc();
        c32 pre = colA[0 * 2 + ((tid >> 8) & 1)];
#pragma unroll
        for (int w = 1; w < 8; w++) pre = cmul(pre, colA[w * 2 + ((tid >> (8 - w)) & 1)]);
        c32 ph[4];
#pragma unroll
        for (int t = 0; t < 4; t++)
            ph[t] = cmul(pre, cmul(colA[8 * 2 + (t >> 1)], colA[9 * 2 + (t & 1)]));
        const int t0b = tid & 1;                  // runtime bit 4 of x
        c32 phe[4];
#pragma unroll
        for (int t = 0; t < 4; t++) phe[t] = t0b ? ph[t ^ 2] : ph[t];
        c32 t2[4];
#pragma unroll
        for (int t = 0; t < 4; t++) t2[t] = cmul(colA[10 * 2 + (t >> 1)], colA[11 * 2 + (t & 1)]);
        c32 pl[8];
#pragma unroll
        for (int u = 0; u < 8; u++) pl[u] = cmul(t2[u >> 1], colA[12 * 2 + (u & 1)]);

        u64 reg[16];
#pragma unroll
        for (int j = 0; j < 16; j++) {
            const int cj = qc.combo[2][j];
            const c32 v = cmul(phe[(cj >> 3) & 3], pl[cj & 7]);
            reg[j] = pk2(v.x, v.y);
        }
        const int x = tid << 4;
        apply_batch_gates<2>(reg, sspl, x);
#pragma unroll
        for (int j = 0; j < 16; j++) s64[sw(x ^ qc.combo[2][j])] = reg[j];
    }
    __syncthreads();

    // ---- remaining layer-2 gate batches ----
    do_batch<0>(s64, sspl, tid); __syncthreads();
    do_batch<1>(s64, sspl, tid); __syncthreads();

    // ---- final gate (wire 12) fused with <Z_w> via compile-time WHT signs ----
    {
        constexpr QCData qc = make_qc();
        constexpr int m12 = qc.m2[12];
        constexpr int r12 = qc.r2[12];
        const u64* Sg = sspl + 12 * 8;
        const u64 a0 = Sg[0], a1 = Sg[1], a2 = Sg[2], a3 = Sg[3];
        const u64 a4 = Sg[4], a5 = Sg[5], a6 = Sg[6], a7 = Sg[7];
        const int  x0 = tid << 1;                 // insert(tid), lomask==0
        const bool o0 = (__popc(x0 & r12) & 1) != 0;
        const u64 E0xx = o0 ? a6 : a0, E0yn = o0 ? a7 : a1;
        const u64 E1xx = o0 ? a4 : a2, E1yn = o0 ? a5 : a3;
        const u64 E2xx = o0 ? a2 : a4, E2yn = o0 ? a3 : a5;
        const u64 E3xx = o0 ? a0 : a6, E3yn = o0 ? a1 : a7;

        float p[16];
#pragma unroll
        for (int jj = 0; jj < 8; jj++) {
            const int x  = x0 ^ (jj << 10);
            const int xp = x ^ m12;
            const u64 va = s64[sw(x)], vb = s64[sw(xp)];
            const u64 vas = swp2(va), vbs = swp2(vb);
            const bool od = qc.odm[jj] != 0;       // compile-time renaming
            const u64 m00xx = od ? E3xx : E0xx, m00yn = od ? E3yn : E0yn;
            const u64 m01xx = od ? E2xx : E1xx, m01yn = od ? E2yn : E1yn;
            const u64 m10xx = od ? E1xx : E2xx, m10yn = od ? E1yn : E2yn;
            const u64 m11xx = od ? E0xx : E3xx, m11yn = od ? E0yn : E3yn;
            const u64 n0 = bfly(va, vas, vb, vbs, m00xx, m00yn, m01xx, m01yn);
            const u64 n1 = bfly(va, vas, vb, vbs, m10xx, m10yn, m11xx, m11yn);
            float n0x, n0y, n1x, n1y;
            upk2(n0, n0x, n0y); upk2(n1, n1x, n1y);
            p[jj]     = fmaf(n0x, n0x, n0y * n0y);   // prob at index x
            p[jj | 8] = fmaf(n1x, n1x, n1y * n1y);   // prob at index x^m
        }
        // 16-point Walsh–Hadamard (all signs compile-time)
#pragma unroll
        for (int st = 1; st < 16; st <<= 1) {
#pragma unroll
            for (int k = 0; k < 16; k++)
                if (!(k & st)) {
                    const float a = p[k], b = p[k ^ st];
                    p[k] = a + b; p[k ^ st] = a - b;
                }
        }
        int sig0 = 0;
#pragma unroll
        for (int w = 0; w < P; w++) sig0 |= (__popc(x0 & qc.rm[w]) & 1) << w;

        // All state reads are done; state region becomes reduction scratch.
        __syncthreads();
#pragma unroll
        for (int w = 0; w < P; w++) {
            float v = p[qc.kw[w]];
            v = ((sig0 >> w) & 1) ? -v : v;
            scr[w * TPB + tid] = v;               // consecutive lanes: conflict-free
        }
    }
    __syncthreads();

    // warps 0..12: warp w reduces wire w (16 strided conflict-free loads + shfl tree)
    if (wid < P) {
        float acc = 0.0f;
#pragma unroll
        for (int j = 0; j < 16; j++) acc += scr[wid * TPB + lane + 32 * j];
#pragma unroll
        for (int off = 16; off; off >>= 1)
            acc += __shfl_xor_sync(0xffffffffu, acc, off);
        if (lane == 0) expv[wid] = acc;
    }
    __syncthreads();

    // ---- decode + residual ----
    const float al = alpha[0];
    const int base = n * P * D;
    for (int e = tid; e < P * D; e += TPB) {
        const int w = e >> 6;
        const int d = e & 63;
        out[base + e] = h[base + e] + al * expv[w] * dec_w[d];
    }
}

} // anonymous namespace

extern "C" void kernel_launch(void* const* d_in, const int* in_sizes, int n_in,
                              void* d_out, int out_size)
{
    const float* h     = (const float*)d_in[0];
    const float* enc_w = (const float*)d_in[1];
    const float* enc_b = (const float*)d_in[2];
    const float* qw    = (const float*)d_in[3];
    const float* dec_w = (const float*)d_in[4];
    const float* alpha = (const float*)d_in[5];
    float* out = (float*)d_out;

    const int nsamp = in_sizes[0] / (P * D);   // B*T

    cudaFuncSetAttribute(qlc_kernel, cudaFuncAttributeMaxDynamicSharedMemorySize, SMEM_BYTES);
    qlc_kernel<<<nsamp, TPB, SMEM_BYTES>>>(h, enc_w, enc_b, qw, dec_w, alpha, out);
}

// round 17
// speedup vs baseline: 1.1383x; 1.1383x over previous
#include <cuda_runtime.h>
#include <math.h>

namespace {

constexpr int P     = 13;
constexpr int TPB   = 512;
constexpr int D     = 64;
constexpr int NWARP = TPB / 32;

struct c32 { float x, y; };
typedef unsigned long long u64;

__device__ __forceinline__ c32 cmul(c32 a, c32 b) {
    return { fmaf(a.x, b.x, -a.y * b.y), fmaf(a.x, b.y, a.y * b.x) };
}
__device__ __forceinline__ c32 cadd(c32 a, c32 b) { return { a.x + b.x, a.y + b.y }; }

// ---------------- packed f32x2 helpers ----------------
__device__ __forceinline__ u64 pk2(float x, float y) {
    u64 r; asm("mov.b64 %0, {%1, %2};" : "=l"(r) : "f"(x), "f"(y)); return r;
}
__device__ __forceinline__ void upk2(u64 v, float& x, float& y) {
    asm("mov.b64 {%0, %1}, %2;" : "=f"(x), "=f"(y) : "l"(v));
}
__device__ __forceinline__ u64 swp2(u64 v) {
    u64 r;
    asm("{ .reg .b32 lo, hi; mov.b64 {lo, hi}, %1; mov.b64 %0, {hi, lo}; }"
        : "=l"(r) : "l"(v));
    return r;
}
__device__ __forceinline__ u64 mul2(u64 a, u64 b) {
    u64 r; asm("mul.rn.f32x2 %0, %1, %2;" : "=l"(r) : "l"(a), "l"(b)); return r;
}
__device__ __forceinline__ u64 fma2(u64 a, u64 b, u64 c) {
    u64 r; asm("fma.rn.f32x2 %0, %1, %2, %3;" : "=l"(r) : "l"(a), "l"(b), "l"(c)); return r;
}
__device__ __forceinline__ u64 splat_xx(c32 m) {
    u64 r; asm("mov.b64 %0, {%1, %1};" : "=l"(r) : "f"(m.x)); return r;
}
__device__ __forceinline__ u64 splat_yn(c32 m) {
    u64 r; asm("mov.b64 %0, {%1, %2};" : "=l"(r) : "f"(-m.y), "f"(m.y)); return r;
}
// n = m0*va + m1*vb  (complex, packed):  va,vb packed {x,y}; vas,vbs their swaps {y,x}
__device__ __forceinline__ u64 bfly(u64 va, u64 vas, u64 vb, u64 vbs,
                                    u64 m0xx, u64 m0yn, u64 m1xx, u64 m1yn) {
    return fma2(va, m0xx, fma2(vas, m0yn, fma2(vb, m1xx, mul2(vbs, m1yn))));
}

// ---------------- compile-time GF(2) machinery ----------------

__host__ __device__ constexpr int cg_cnot(int i, int x) {
    int cb = P - 1 - i;
    int tb = P - 1 - ((i + 1) % P);
    return ((x >> cb) & 1) ? (x ^ (1 << tb)) : x;
}
__host__ __device__ constexpr int cGmap(int y) {
    for (int i = P - 1; i >= 0; --i) y = cg_cnot(i, y);
    return y;
}
__host__ __device__ constexpr int cGinv(int y) {
    for (int i = 0; i < P; i++) y = cg_cnot(i, y);
    return y;
}
__host__ __device__ constexpr int cpop(int x) { int c = 0; for (int i = 0; i < 16; i++) c += (x >> i) & 1; return c; }
__host__ __device__ constexpr int cctz(int x) { for (int i = 0; i < 16; i++) if ((x >> i) & 1) return i; return -1; }

struct QCData {
    int m2[P];            // layer-2 pair masks  G(e_w)
    int r2[P];            // layer-2 orientation masks (rows of G^-1)
    int rm[P];            // measurement parity masks (rows of G^-2)
    int npos[3][9];       // non-pivot bit positions per batch (ascending)
    int combo[3][16];     // XOR offsets of the 16 coset members
    int lm[3][4];         // local 4-bit pair pattern per gate
    int lml[3][4];        // lowest set bit of lm (canonical selector)
    int lr[3][4];         // local parity pattern per gate
    int rw[3][4];         // full orientation mask per gate (for px)
    int odm[8];           // measurement: per-jj orientation delta (compile-time)
    int mg[4];            // measurement: WHT sig generators
    int kw[P];            // measurement: WHT coefficient index per wire
};

__host__ __device__ constexpr QCData make_qc() {
    QCData q{};
    for (int w = 0; w < P; w++) {
        q.m2[w] = cGmap(1 << (P - 1 - w));
        int r = 0, rm = 0;
        for (int p = 0; p < P; p++) {
            int gi  = cGinv(1 << p);
            int gi2 = cGinv(gi);
            r  |= ((gi  >> (P - 1 - w)) & 1) << p;
            rm |= ((gi2 >> (P - 1 - w)) & 1) << p;
        }
        q.r2[w] = r; q.rm[w] = rm;
    }
    for (int b = 0; b < 3; b++) {
        int f[4] = {}, piv[4] = {};
        for (int i = 0; i < 4; i++) f[i] = q.m2[4 * b + i];
        for (int i = 0; i < 4; i++) {
            for (int j = 0; j < i; j++) if ((f[i] >> piv[j]) & 1) f[i] ^= f[j];
            piv[i] = cctz(f[i]);
            for (int j = 0; j < i; j++) if ((f[j] >> piv[i]) & 1) f[j] ^= f[i];
        }
        int np = 0;
        for (int bit = 0; bit < P; bit++) {
            bool isp = false;
            for (int i = 0; i < 4; i++) if (piv[i] == bit) isp = true;
            if (!isp) q.npos[b][np++] = bit;
        }
        for (int j = 0; j < 16; j++) {
            int c = 0;
            for (int i = 0; i < 4; i++) if ((j >> i) & 1) c ^= f[i];
            q.combo[b][j] = c;
        }
        for (int g = 0; g < 4; g++) {
            int m = q.m2[4 * b + g], r = q.r2[4 * b + g];
            int lm = 0, lr = 0;
            for (int i = 0; i < 4; i++) {
                lm |= ((m >> piv[i]) & 1) << i;
                lr |= (cpop(f[i] & r) & 1) << i;
            }
            q.lm[b][g] = lm;
            q.lml[b][g] = lm & (-lm);
            q.lr[b][g] = lr;
            q.rw[b][g] = r;
        }
    }
    // measurement constants (final gate on wire 12 fused with <Z> readout)
    {
        int m12 = q.m2[12], r12 = q.r2[12];
        for (int jj = 0; jj < 8; jj++) q.odm[jj] = cpop((jj << 10) & r12) & 1;
        for (int i = 0; i < 4; i++) {
            int v = (i < 3) ? (1024 << i) : m12;    // idx-bit deltas in amp-index space
            int sgn = 0;
            for (int w = 0; w < P; w++) sgn |= (cpop(v & q.rm[w]) & 1) << w;
            q.mg[i] = sgn;
        }
        for (int w = 0; w < P; w++) {
            int k = 0;
            for (int i = 0; i < 4; i++) k |= ((q.mg[i] >> w) & 1) << i;
            q.kw[w] = k;
        }
    }
    return q;
}

// host-side structural checks only (device code re-materializes its own local constexpr copy)
constexpr QCData QC_HOST = make_qc();
__host__ __device__ constexpr int batch2_support() {
    int s = 0;
    for (int j = 0; j < 16; j++) s |= QC_HOST.combo[2][j];
    return s;
}
static_assert((QC_HOST.m2[12] & 1) == 1, "insert for final gate must be <<1");
static_assert(QC_HOST.npos[2][0] == 4 && QC_HOST.npos[2][8] == 12, "batch2 coset must be low-bit");
static_assert((batch2_support() & ~0x1F) == 0, "batch2 combos must live in bits 0..4");

// SMEM bank-conflict swizzle: XOR bits[7:4] into bits[3:0]. Bijection on [0,8192).
__device__ __forceinline__ int sw(int y) { return y ^ ((y >> 4) & 0xF); }

// ---------------- SMEM layout (floats) ----------------
constexpr int SM_S    = 0;                    // 8192 c32 = 16384 floats
constexpr int SM_COLA = 16384;                // 13*2 c32 = 52 floats (8B aligned)
constexpr int SM_MATB = 16436;                // 13*8 = 104 floats (8B aligned)
constexpr int SM_WSUM = 16540;                // NWARP*13 = 208
constexpr int SM_EXPV = 16748;                // 13
constexpr int SMEM_BYTES = (16748 + 13 + 3) * 4;

// Apply 4 masked gates of batch B to the 16-amp packed register coset.
template <int B>
__device__ __forceinline__ void apply_batch_gates(u64* __restrict__ reg,
                                                  const float* __restrict__ matB, int x)
{
    constexpr QCData qc = make_qc();
#pragma unroll
    for (int g = 0; g < 4; g++) {
        const int w = 4 * B + g;
        const float* M = matB + w * 8;
        const c32 u00 = { M[0], M[1] }, u01 = { M[2], M[3] };
        const c32 u10 = { M[4], M[5] }, u11 = { M[6], M[7] };
        const bool px = (__popc(x & qc.rw[B][g]) & 1) != 0;
        const c32 e00 = px ? u11 : u00, e01 = px ? u10 : u01;
        const c32 e10 = px ? u01 : u10, e11 = px ? u00 : u11;
        const u64 E0xx = splat_xx(e00), E0yn = splat_yn(e00);
        const u64 E1xx = splat_xx(e01), E1yn = splat_yn(e01);
        const u64 E2xx = splat_xx(e10), E2yn = splat_yn(e10);
        const u64 E3xx = splat_xx(e11), E3yn = splat_yn(e11);
#pragma unroll
        for (int j = 0; j < 16; j++) {
            if (j & qc.lml[B][g]) continue;                  // canonical of each pair
            const int jp  = j ^ qc.lm[B][g];                 // compile-time partner
            const bool oc = (cpop(j & qc.lr[B][g]) & 1) != 0; // compile-time
            const u64 m00xx = oc ? E3xx : E0xx, m00yn = oc ? E3yn : E0yn;
            const u64 m01xx = oc ? E2xx : E1xx, m01yn = oc ? E2yn : E1yn;
            const u64 m10xx = oc ? E1xx : E2xx, m10yn = oc ? E1yn : E2yn;
            const u64 m11xx = oc ? E0xx : E3xx, m11yn = oc ? E0yn : E3yn;
            const u64 va = reg[j], vb = reg[jp];
            const u64 vas = swp2(va), vbs = swp2(vb);
            reg[j]  = bfly(va, vas, vb, vbs, m00xx, m00yn, m01xx, m01yn);
            reg[jp] = bfly(va, vas, vb, vbs, m10xx, m10yn, m11xx, m11yn);
        }
    }
}

template <int B>
__device__ __forceinline__ void do_batch(u64* __restrict__ s64,
                                         const float* __restrict__ matB, int tid)
{
    constexpr QCData qc = make_qc();
    int x = 0;
#pragma unroll
    for (int i = 0; i < 9; i++) x |= ((tid >> i) & 1) << qc.npos[B][i];

    u64 reg[16];
#pragma unroll
    for (int j = 0; j < 16; j++) reg[j] = s64[sw(x ^ qc.combo[B][j])];

    apply_batch_gates<B>(reg, matB, x);

#pragma unroll
    for (int j = 0; j < 16; j++) s64[sw(x ^ qc.combo[B][j])] = reg[j];
}

__global__ void __launch_bounds__(TPB, 2)
qlc_kernel(const float* __restrict__ h,
           const float* __restrict__ enc_w,
           const float* __restrict__ enc_b,
           const float* __restrict__ qw,
           const float* __restrict__ dec_w,
           const float* __restrict__ alpha,
           float* __restrict__ out)
{
    extern __shared__ float smemf[];
    u64*   s64  = (u64*)(smemf + SM_S);
    c32*   colA = (c32*)(smemf + SM_COLA);   // [13][2] fused (enc+L1) column-0
    float* matB = smemf + SM_MATB;           // [13][8] layer-2 gate matrices
    float* wsum = smemf + SM_WSUM;
    float* expv = smemf + SM_EXPV;

    const int n = blockIdx.x, tid = threadIdx.x, wid = tid >> 5, lane = tid & 31;

    // ================= Phase A (fully parallel constants, fast sincos) =================
    // warps 0..12: wire w = wid — warp-reduced angles, lane 0 builds colA[w].
    // warp 13 lanes 0..12: shared layer-2 gate matrices (concurrent).
    if (wid < P) {
        const float* hrow = h + (n * P + wid) * D;
        const float h0 = hrow[lane], h1 = hrow[lane + 32];
        float aa[3];
#pragma unroll
        for (int a = 0; a < 3; a++) {
            float v = h0 * enc_w[a * D + lane] + h1 * enc_w[a * D + lane + 32];
#pragma unroll
            for (int off = 16; off; off >>= 1)
                v += __shfl_xor_sync(0xffffffffu, v, off);
            aa[a] = v;
        }
        if (lane == 0) {
            const int w = wid;
            float a0 = aa[0] + enc_b[0], a1 = aa[1] + enc_b[1], a2 = aa[2] + enc_b[2];
            float q0 = qw[w * 3 + 0], q1 = qw[w * 3 + 1], q2 = qw[w * 3 + 2];  // layer 0
            float sA, cA; __sincosf(0.5f * a0, &sA, &cA);
            c32 v0 = { cA, 0.f }, v1 = { 0.f, -sA };                 // RX col0
            float sB, cB; __sincosf(0.5f * a1, &sB, &cB);            // RY
            c32 t0 = { cB * v0.x - sB * v1.x, cB * v0.y - sB * v1.y };
            c32 t1 = { sB * v0.x + cB * v1.x, sB * v0.y + cB * v1.y };
            float sC, cC; __sincosf(0.5f * a2, &sC, &cC);            // RZ
            v0 = cmul({ cC, -sC }, t0); v1 = cmul({ cC, sC }, t1);
            float s0, c0; __sincosf(0.5f * q0, &s0, &c0);            // RY
            t0 = { c0 * v0.x - s0 * v1.x, c0 * v0.y - s0 * v1.y };
            t1 = { s0 * v0.x + c0 * v1.x, s0 * v0.y + c0 * v1.y };
            float s1, c1; __sincosf(0.5f * q1, &s1, &c1);            // RZ
            v0 = cmul({ c1, -s1 }, t0); v1 = cmul({ c1, s1 }, t1);
            float s2, c2; __sincosf(0.5f * q2, &s2, &c2);            // RY
            t0 = { c2 * v0.x - s2 * v1.x, c2 * v0.y - s2 * v1.y };
            t1 = { s2 * v0.x + c2 * v1.x, s2 * v0.y + c2 * v1.y };
            colA[w * 2 + 0] = t0; colA[w * 2 + 1] = t1;
        }
    } else if (wid == 13 && lane < P) {
        const int w = lane;
        float q0 = qw[(P + w) * 3 + 0], q1 = qw[(P + w) * 3 + 1], q2 = qw[(P + w) * 3 + 2]; // layer 1
        float s0, c0; __sincosf(0.5f * q0, &s0, &c0);
        float s1, c1; __sincosf(0.5f * q1, &s1, &c1);
        float s2, c2; __sincosf(0.5f * q2, &s2, &c2);
        // M1 = RZ(q1)*RY(q0)
        c32 e0 = { c1, -s1 }, e1 = { c1, s1 };
        c32 m00 = {  e0.x * c0,  e0.y * c0 }, m01 = { -e0.x * s0, -e0.y * s0 };
        c32 m10 = {  e1.x * s0,  e1.y * s0 }, m11 = {  e1.x * c0,  e1.y * c0 };
        // U = RY(q2)*M1
        c32 u00 = { c2 * m00.x - s2 * m10.x, c2 * m00.y - s2 * m10.y };
        c32 u01 = { c2 * m01.x - s2 * m11.x, c2 * m01.y - s2 * m11.y };
        c32 u10 = { s2 * m00.x + c2 * m10.x, s2 * m00.y + c2 * m10.y };
        c32 u11 = { s2 * m01.x + c2 * m11.x, s2 * m01.y + c2 * m11.y };
        float* M = matB + w * 8;
        M[0] = u00.x; M[1] = u00.y; M[2] = u01.x; M[3] = u01.y;
        M[4] = u10.x; M[5] = u10.y; M[6] = u11.x; M[7] = u11.y;
    }
    __syncthreads();

    // ---- product-state construction FUSED with batch-2 gates (registers only) ----
    {
        constexpr QCData qc = make_qc();
        // x = tid<<4 (batch-2 coset representative; static_asserted structure).
        c32 pre = colA[0 * 2 + ((tid >> 8) & 1)];
#pragma unroll
        for (int w = 1; w < 8; w++) pre = cmul(pre, colA[w * 2 + ((tid >> (8 - w)) & 1)]);
        c32 ph[4];
#pragma unroll
        for (int t = 0; t < 4; t++)
            ph[t] = cmul(pre, cmul(colA[8 * 2 + (t >> 1)], colA[9 * 2 + (t & 1)]));
        const int t0b = tid & 1;                  // runtime bit 4 of x
        c32 phe[4];
#pragma unroll
        for (int t = 0; t < 4; t++) phe[t] = t0b ? ph[t ^ 2] : ph[t];
        c32 t2[4];
#pragma unroll
        for (int t = 0; t < 4; t++) t2[t] = cmul(colA[10 * 2 + (t >> 1)], colA[11 * 2 + (t & 1)]);
        c32 pl[8];
#pragma unroll
        for (int u = 0; u < 8; u++) pl[u] = cmul(t2[u >> 1], colA[12 * 2 + (u & 1)]);

        u64 reg[16];
#pragma unroll
        for (int j = 0; j < 16; j++) {
            const int cj = qc.combo[2][j];
            const c32 v = cmul(phe[(cj >> 3) & 3], pl[cj & 7]);
            reg[j] = pk2(v.x, v.y);
        }
        const int x = tid << 4;
        apply_batch_gates<2>(reg, matB, x);
#pragma unroll
        for (int j = 0; j < 16; j++) s64[sw(x ^ qc.combo[2][j])] = reg[j];
    }
    __syncthreads();

    // ---- remaining layer-2 gate batches ----
    do_batch<0>(s64, matB, tid); __syncthreads();
    do_batch<1>(s64, matB, tid); __syncthreads();

    // ---- final gate (wire 12) fused with <Z_w> via compile-time WHT signs ----
    {
        constexpr QCData qc = make_qc();
        constexpr int m12 = qc.m2[12];
        constexpr int r12 = qc.r2[12];
        const float* M = matB + 12 * 8;
        const c32 u00 = { M[0], M[1] }, u01 = { M[2], M[3] };
        const c32 u10 = { M[4], M[5] }, u11 = { M[6], M[7] };
        const int  x0 = tid << 1;                 // insert(tid), lomask==0
        const bool o0 = (__popc(x0 & r12) & 1) != 0;
        const c32 e00 = o0 ? u11 : u00, e01 = o0 ? u10 : u01;
        const c32 e10 = o0 ? u01 : u10, e11 = o0 ? u00 : u11;
        const u64 E0xx = splat_xx(e00), E0yn = splat_yn(e00);
        const u64 E1xx = splat_xx(e01), E1yn = splat_yn(e01);
        const u64 E2xx = splat_xx(e10), E2yn = splat_yn(e10);
        const u64 E3xx = splat_xx(e11), E3yn = splat_yn(e11);

        float p[16];
#pragma unroll
        for (int jj = 0; jj < 8; jj++) {
            const int x  = x0 ^ (jj << 10);
            const int xp = x ^ m12;
            const u64 va = s64[sw(x)], vb = s64[sw(xp)];
            const u64 vas = swp2(va), vbs = swp2(vb);
            const bool od = qc.odm[jj] != 0;       // compile-time
            const u64 m00xx = od ? E3xx : E0xx, m00yn = od ? E3yn : E0yn;
            const u64 m01xx = od ? E2xx : E1xx, m01yn = od ? E2yn : E1yn;
            const u64 m10xx = od ? E1xx : E2xx, m10yn = od ? E1yn : E2yn;
            const u64 m11xx = od ? E0xx : E3xx, m11yn = od ? E0yn : E3yn;
            const u64 n0 = bfly(va, vas, vb, vbs, m00xx, m00yn, m01xx, m01yn);
            const u64 n1 = bfly(va, vas, vb, vbs, m10xx, m10yn, m11xx, m11yn);
            float n0x, n0y, n1x, n1y;
            upk2(n0, n0x, n0y); upk2(n1, n1x, n1y);
            p[jj]     = fmaf(n0x, n0x, n0y * n0y);   // prob at index x
            p[jj | 8] = fmaf(n1x, n1x, n1y * n1y);   // prob at index x^m
        }
        // 16-point Walsh–Hadamard (all signs compile-time)
#pragma unroll
        for (int st = 1; st < 16; st <<= 1) {
#pragma unroll
            for (int k = 0; k < 16; k++)
                if (!(k & st)) {
                    const float a = p[k], b = p[k ^ st];
                    p[k] = a + b; p[k ^ st] = a - b;
                }
        }
        int sig0 = 0;
#pragma unroll
        for (int w = 0; w < P; w++) sig0 |= (__popc(x0 & qc.rm[w]) & 1) << w;
#pragma unroll
        for (int w = 0; w < P; w++) {
            float v = p[qc.kw[w]];
            v = ((sig0 >> w) & 1) ? -v : v;
#pragma unroll
            for (int off = 16; off; off >>= 1)
                v += __shfl_xor_sync(0xffffffffu, v, off);
            if (lane == 0) wsum[wid * P + w] = v;
        }
    }
    __syncthreads();
    if (tid < P) {
        float v = 0.0f;
        for (int k = 0; k < NWARP; k++) v += wsum[k * P + tid];
        expv[tid] = v;
    }
    __syncthreads();

    // ---- decode + residual ----
    const float al = alpha[0];
    const int base = n * P * D;
    for (int e = tid; e < P * D; e += TPB) {
        const int w = e >> 6;
        const int d = e & 63;
        out[base + e] = h[base + e] + al * expv[w] * dec_w[d];
    }
}

} // anonymous namespace

extern "C" void kernel_launch(void* const* d_in, const int* in_sizes, int n_in,
                              void* d_out, int out_size)
{
    const float* h     = (const float*)d_in[0];
    const float* enc_w = (const float*)d_in[1];
    const float* enc_b = (const float*)d_in[2];
    const float* qw    = (const float*)d_in[3];
    const float* dec_w = (const float*)d_in[4];
    const float* alpha = (const float*)d_in[5];
    float* out = (float*)d_out;

    const int nsamp = in_sizes[0] / (P * D);   // B*T

    cudaFuncSetAttribute(qlc_kernel, cudaFuncAttributeMaxDynamicSharedMemorySize, SMEM_BYTES);
    qlc_kernel<<<nsamp, TPB, SMEM_BYTES>>>(h, enc_w, enc_b, qw, dec_w, alpha, out);
}